// round 1
// baseline (speedup 1.0000x reference)
#include <cuda_runtime.h>
#include <cuda_bf16.h>
#include <cstdint>

// ---------------------------------------------------------------------------
// BitNetSummaryEncoder
//   combined[51] = [cemb[rc], cemb[wc], cemb[fc], cemb[cc], remb[r],
//                   ternMLP(vol)(6), ternMLP(pres)(20)]
//   h = combined @ f_wh.T + f_bh ; g = sigmoid(combined @ f_wg.T + f_bg)
//   out = layernorm(g*h) * ln_g + ln_b
//
// Round-1 baseline: fp32, FFMA2-packed (h,g) GEMV, thread-per-row,
// weights (wh,wg interleaved) in smem, LN via smem-transposed staging +
// L2-hot readback normalize pass.
// ---------------------------------------------------------------------------

#define TILE_ROWS 256
#define DOUT 256
#define KTOT 51
#define KPAD 52   // padded pair count (pad entry is zero)

// quantized small ternary weights: vw1q[32] | vw2q[48] | pw1q[288] | pw2q[480]
__device__ float d_q[848];

// ---- packed f32x2 helpers (Blackwell FFMA2 path) --------------------------
__device__ __forceinline__ unsigned long long pk2(float a, float b) {
    unsigned long long r;
    asm("mov.b64 %0, {%1, %2};" : "=l"(r) : "f"(a), "f"(b));
    return r;
}
__device__ __forceinline__ void upk2(unsigned long long v, float& a, float& b) {
    asm("mov.b64 {%0, %1}, %2;" : "=f"(a), "=f"(b) : "l"(v));
}
__device__ __forceinline__ unsigned long long fma2(unsigned long long a,
                                                   unsigned long long b,
                                                   unsigned long long c) {
    unsigned long long d;
    asm("fma.rn.f32x2 %0, %1, %2, %3;" : "=l"(d) : "l"(a), "l"(b), "l"(c));
    return d;
}
__device__ __forceinline__ unsigned long long add2(unsigned long long a,
                                                   unsigned long long b) {
    unsigned long long d;
    asm("add.rn.f32x2 %0, %1, %2;" : "=l"(d) : "l"(a), "l"(b));
    return d;
}

__device__ __forceinline__ float gelu_exact(float x) {
    return 0.5f * x * (1.0f + erff(x * 0.7071067811865476f));
}

// ---------------------------------------------------------------------------
// Prep kernel: BitNet ternary quantization of the 4 small MLP weights.
// Wq = clip(round(W / (mean|W| + 1e-5)), -1, 1) * mean|W|
// ---------------------------------------------------------------------------
__global__ void quant_prep_kernel(const float* __restrict__ vw1,
                                  const float* __restrict__ vw2,
                                  const float* __restrict__ pw1,
                                  const float* __restrict__ pw2) {
    __shared__ float red[512];
    const float* W;
    int n;
    float* out;
    switch (blockIdx.x) {
        case 0:  W = vw1; n = 32;  out = d_q;       break;
        case 1:  W = vw2; n = 48;  out = d_q + 32;  break;
        case 2:  W = pw1; n = 288; out = d_q + 80;  break;
        default: W = pw2; n = 480; out = d_q + 368; break;
    }
    int t = threadIdx.x;
    float v = (t < n) ? fabsf(W[t]) : 0.0f;
    red[t] = v;
    __syncthreads();
#pragma unroll
    for (int s = 256; s > 0; s >>= 1) {
        if (t < s) red[t] += red[t + s];
        __syncthreads();
    }
    float scale = red[0] / (float)n;
    if (t < n) {
        float q = rintf(W[t] / (scale + 1e-5f));  // rintf == banker's rounding (jnp.round)
        q = fminf(fmaxf(q, -1.0f), 1.0f);
        out[t] = q * scale;
    }
}

// ---------------------------------------------------------------------------
// smem layout (float offsets)
// ---------------------------------------------------------------------------
#define OFF_W     0                    // 256 * 52 float2 (wh,wg interleaved) = 26624 f
#define OFF_Z     26624                // zbuf: 256 * 65                     = 16640 f
#define OFF_BHG   43264                // 256 float2 (bh,bg)                 =   512 f
#define OFF_LNG   43776                // 256
#define OFF_LNB   44032                // 256
#define OFF_CEMB  44288                // 320
#define OFF_REMB  44608                // 320
#define OFF_Q     44928                // 848
#define OFF_SB    45776                // small biases: vb1[8]@0 vb2[6]@8 pb1[24]@16 pb2[20]@40 (64)
#define SMEM_FLOATS 45840
#define SMEM_BYTES  (SMEM_FLOATS * 4)

__global__ void __launch_bounds__(256, 1)
encoder_main_kernel(const int* __restrict__ read_count,
                    const int* __restrict__ write_count,
                    const int* __restrict__ fault_count,
                    const int* __restrict__ cow_count,
                    const int* __restrict__ recency,
                    const float* __restrict__ volatility,
                    const float* __restrict__ pressure,
                    const float* __restrict__ count_emb,
                    const float* __restrict__ recency_emb,
                    const float* __restrict__ p_b1,
                    const float* __restrict__ p_b2,
                    const float* __restrict__ v_b1,
                    const float* __restrict__ v_b2,
                    const float* __restrict__ f_wh,
                    const float* __restrict__ f_bh,
                    const float* __restrict__ f_wg,
                    const float* __restrict__ f_bg,
                    const float* __restrict__ ln_g,
                    const float* __restrict__ ln_b,
                    float* __restrict__ out) {
    extern __shared__ float smem[];
    const int tid = threadIdx.x;

    // ---- stage shared parameters --------------------------------------
    float2* s_w2 = (float2*)(smem + OFF_W);
    for (int i = tid; i < DOUT * KTOT; i += 256) {
        int o = i / KTOT;
        int k = i - o * KTOT;
        s_w2[o * KPAD + k] = make_float2(f_wh[i], f_wg[i]);
    }
    s_w2[tid * KPAD + 51] = make_float2(0.0f, 0.0f);  // zero pad (tid == o, 256 each)
    ((float2*)(smem + OFF_BHG))[tid] = make_float2(f_bh[tid], f_bg[tid]);
    smem[OFF_LNG + tid] = ln_g[tid];
    smem[OFF_LNB + tid] = ln_b[tid];
    for (int i = tid; i < 320; i += 256) {
        smem[OFF_CEMB + i] = count_emb[i];
        smem[OFF_REMB + i] = recency_emb[i];
    }
    for (int i = tid; i < 848; i += 256) smem[OFF_Q + i] = d_q[i];
    if (tid < 8)  smem[OFF_SB + tid]      = v_b1[tid];
    if (tid < 6)  smem[OFF_SB + 8 + tid]  = v_b2[tid];
    if (tid < 24) smem[OFF_SB + 16 + tid] = p_b1[tid];
    if (tid < 20) smem[OFF_SB + 40 + tid] = p_b2[tid];
    __syncthreads();

    const float* s_q  = smem + OFF_Q;
    const float* s_sb = smem + OFF_SB;

    // ---- phase 0: per-row combined[52] packed into registers ----------
    const size_t row = (size_t)blockIdx.x * TILE_ROWS + tid;

    const int rc = read_count[row];
    const int wc = write_count[row];
    const int fc = fault_count[row];
    const int cc = cow_count[row];
    const int rr = recency[row];

    float4 v4 = ((const float4*)volatility)[row];
    float va[4] = {v4.x, v4.y, v4.z, v4.w};
    float4 pA = ((const float4*)pressure)[row * 3 + 0];
    float4 pB = ((const float4*)pressure)[row * 3 + 1];
    float4 pC = ((const float4*)pressure)[row * 3 + 2];
    float pr[12] = {pA.x, pA.y, pA.z, pA.w, pB.x, pB.y, pB.z, pB.w,
                    pC.x, pC.y, pC.z, pC.w};

    float v1[8];
#pragma unroll
    for (int j = 0; j < 8; j++) {
        float a = s_sb[j];
#pragma unroll
        for (int i = 0; i < 4; i++) a = fmaf(s_q[j * 4 + i], va[i], a);
        v1[j] = gelu_exact(a);
    }
    float pv[6];
#pragma unroll
    for (int j = 0; j < 6; j++) {
        float a = s_sb[8 + j];
#pragma unroll
        for (int i = 0; i < 8; i++) a = fmaf(s_q[32 + j * 8 + i], v1[i], a);
        pv[j] = a;
    }
    float p1[24];
#pragma unroll
    for (int j = 0; j < 24; j++) {
        float a = s_sb[16 + j];
#pragma unroll
        for (int i = 0; i < 12; i++) a = fmaf(s_q[80 + j * 12 + i], pr[i], a);
        p1[j] = gelu_exact(a);
    }
    float pp[20];
#pragma unroll
    for (int j = 0; j < 20; j++) {
        float a = s_sb[40 + j];
#pragma unroll
        for (int i = 0; i < 24; i++) a = fmaf(s_q[368 + j * 24 + i], p1[i], a);
        pp[j] = a;
    }

    unsigned long long c2[KPAD];
#pragma unroll
    for (int d = 0; d < 5; d++) {
        float e;
        e = smem[OFF_CEMB + rc * 5 + d]; c2[d]      = pk2(e, e);
        e = smem[OFF_CEMB + wc * 5 + d]; c2[5 + d]  = pk2(e, e);
        e = smem[OFF_CEMB + fc * 5 + d]; c2[10 + d] = pk2(e, e);
        e = smem[OFF_CEMB + cc * 5 + d]; c2[15 + d] = pk2(e, e);
        e = smem[OFF_REMB + rr * 5 + d]; c2[20 + d] = pk2(e, e);
    }
#pragma unroll
    for (int j = 0; j < 6; j++)  c2[25 + j] = pk2(pv[j], pv[j]);
#pragma unroll
    for (int j = 0; j < 20; j++) c2[31 + j] = pk2(pp[j], pp[j]);
    c2[51] = 0ULL;

    // ---- phase 1: packed (h,g) GEMV over 256 outputs, chunked staging ---
    const ulonglong2* wv = (const ulonglong2*)(smem + OFF_W);
    const unsigned long long* bhg = (const unsigned long long*)(smem + OFF_BHG);
    float* zbuf = smem + OFF_Z;
    const size_t outbase = (size_t)blockIdx.x * (TILE_ROWS * DOUT);

    float sum = 0.0f, sumsq = 0.0f;
    for (int ch = 0; ch < 4; ch++) {
#pragma unroll 1
        for (int j2 = 0; j2 < 64; j2++) {
            const int o = ch * 64 + j2;
            unsigned long long acc  = bhg[o];  // (bh, bg)
            unsigned long long accb = 0ULL;
            const ulonglong2* wrow = wv + o * 26;
#pragma unroll
            for (int j = 0; j < 26; j++) {
                ulonglong2 w = wrow[j];
                acc  = fma2(c2[2 * j],     w.x, acc);
                accb = fma2(c2[2 * j + 1], w.y, accb);
            }
            float h, g;
            upk2(add2(acc, accb), h, g);
            g = 1.0f / (1.0f + __expf(-g));
            float z = g * h;
            sum += z;
            sumsq = fmaf(z, z, sumsq);
            zbuf[tid * 65 + j2] = z;
        }
        __syncthreads();
        // coalesced staged store of this 64-column chunk (un-normalized z)
        for (int i = tid; i < TILE_ROWS * 64; i += 256) {
            int r = i >> 6;
            int c = i & 63;
            out[outbase + (size_t)r * DOUT + ch * 64 + c] = zbuf[r * 65 + c];
        }
        __syncthreads();
    }

    // ---- phase 2: layernorm (L2-hot readback, fully coalesced) ---------
    float mu  = sum * (1.0f / 256.0f);
    float var = fmaxf(sumsq * (1.0f / 256.0f) - mu * mu, 0.0f);
    float rstd = rsqrtf(var + 1e-5f);
    float2* stats = (float2*)zbuf;
    stats[tid] = make_float2(mu, rstd);
    __syncthreads();

    const float4* lng4 = (const float4*)(smem + OFF_LNG);
    const float4* lnb4 = (const float4*)(smem + OFF_LNB);
    float4* out4 = (float4*)(out + outbase);
    for (int i = tid; i < TILE_ROWS * 64; i += 256) {
        int r  = i >> 6;
        int c4 = i & 63;
        float4 z = out4[(size_t)r * 64 + c4];
        float2 st = stats[r];
        float4 gg = lng4[c4];
        float4 bb = lnb4[c4];
        z.x = (z.x - st.x) * st.y * gg.x + bb.x;
        z.y = (z.y - st.x) * st.y * gg.y + bb.y;
        z.z = (z.z - st.x) * st.y * gg.z + bb.z;
        z.w = (z.w - st.x) * st.y * gg.w + bb.w;
        out4[(size_t)r * 64 + c4] = z;
    }
}

// ---------------------------------------------------------------------------
// launch
// ---------------------------------------------------------------------------
extern "C" void kernel_launch(void* const* d_in, const int* in_sizes, int n_in,
                              void* d_out, int out_size) {
    const int* read_count  = (const int*)d_in[0];
    const int* write_count = (const int*)d_in[1];
    const int* fault_count = (const int*)d_in[2];
    const int* cow_count   = (const int*)d_in[3];
    const int* recency     = (const int*)d_in[4];
    const float* volatility = (const float*)d_in[5];
    const float* pressure   = (const float*)d_in[6];
    const float* count_emb  = (const float*)d_in[7];
    const float* recency_emb = (const float*)d_in[8];
    const float* p_w1 = (const float*)d_in[9];
    const float* p_b1 = (const float*)d_in[10];
    const float* p_w2 = (const float*)d_in[11];
    const float* p_b2 = (const float*)d_in[12];
    const float* v_w1 = (const float*)d_in[13];
    const float* v_b1 = (const float*)d_in[14];
    const float* v_w2 = (const float*)d_in[15];
    const float* v_b2 = (const float*)d_in[16];
    const float* f_wh = (const float*)d_in[17];
    const float* f_bh = (const float*)d_in[18];
    const float* f_wg = (const float*)d_in[19];
    const float* f_bg = (const float*)d_in[20];
    const float* ln_g = (const float*)d_in[21];
    const float* ln_b = (const float*)d_in[22];
    float* out = (float*)d_out;

    const int B = in_sizes[0];
    const int num_tiles = B / TILE_ROWS;  // B = 524288 -> 2048

    quant_prep_kernel<<<4, 512>>>(v_w1, v_w2, p_w1, p_w2);

    cudaFuncSetAttribute(encoder_main_kernel,
                         cudaFuncAttributeMaxDynamicSharedMemorySize, SMEM_BYTES);
    encoder_main_kernel<<<num_tiles, 256, SMEM_BYTES>>>(
        read_count, write_count, fault_count, cow_count, recency,
        volatility, pressure, count_emb, recency_emb,
        p_b1, p_b2, v_b1, v_b2,
        f_wh, f_bh, f_wg, f_bg, ln_g, ln_b, out);
}

// round 3
// speedup vs baseline: 1.8795x; 1.8795x over previous
#include <cuda_runtime.h>
#include <cuda_fp16.h>
#include <cstdint>

// ===========================================================================
// BitNetSummaryEncoder — HMMA (mma.sync.m16n8k16) version.
//   combined[64] = [cemb x4, remb, ternMLP(vol)(6), ternMLP(pres)(20),
//                   1.0 (bias slot, k=51), zeros pad]
//   D[row,512] = A[row,64] @ W[64,512]  with W = [wh|bh ; wg|bg]^T (k-major)
//   3-term fp16 split:  Ahi*Whi + Alo*Whi + Ahi*Wlo
//   epilogue: z = h * sigmoid(g);  out = LN(z) * ln_g + ln_b
// ===========================================================================

#define THREADS       256
#define ROWS_PER_CTA  256
#define ROWS_PER_WARP 32
#define NCHUNKS       32      // 32 chunks x 8 cols = 256 output cols

__device__ float d_q[848];    // quantized ternary weights

// ---------------- smem layout (bytes) --------------------------------------
#define SM_WH   0u            // W hi: 64 k-rows x 512 n x 2B = 65536
#define SM_WL   65536u        // W lo: 65536
#define SM_AH   131072u       // A hi: 8 warps x 32 rows x 128B = 32768
#define SM_AL   163840u       // A lo: 32768
#define SM_PAR  196608u       // params (float offsets below)
#define P_CEMB  0
#define P_REMB  320
#define P_Q     640
#define P_SB    1488
#define P_LNG   1552
#define P_LNB   1808
#define P_END   2064
#define SMEM_BYTES (SM_PAR + P_END * 4)

// ---------------- PTX helpers -----------------------------------------------
__device__ __forceinline__ uint32_t smem_u32(const void* p) {
    uint32_t a;
    asm("{ .reg .u64 t; cvta.to.shared.u64 t, %1; cvt.u32.u64 %0, t; }"
        : "=r"(a) : "l"(p));
    return a;
}
__device__ __forceinline__ void ldsm_x4(uint32_t* r, uint32_t addr) {
    asm volatile("ldmatrix.sync.aligned.m8n8.x4.shared.b16 {%0,%1,%2,%3}, [%4];"
                 : "=r"(r[0]), "=r"(r[1]), "=r"(r[2]), "=r"(r[3]) : "r"(addr));
}
__device__ __forceinline__ void ldsm_x4t(uint32_t* r, uint32_t addr) {
    asm volatile("ldmatrix.sync.aligned.m8n8.x4.trans.shared.b16 {%0,%1,%2,%3}, [%4];"
                 : "=r"(r[0]), "=r"(r[1]), "=r"(r[2]), "=r"(r[3]) : "r"(addr));
}
__device__ __forceinline__ void mma16816(float* d, const uint32_t* a,
                                         const uint32_t* b) {
    asm volatile(
        "mma.sync.aligned.m16n8k16.row.col.f32.f16.f16.f32 "
        "{%0,%1,%2,%3}, {%4,%5,%6,%7}, {%8,%9}, {%0,%1,%2,%3};"
        : "+f"(d[0]), "+f"(d[1]), "+f"(d[2]), "+f"(d[3])
        : "r"(a[0]), "r"(a[1]), "r"(a[2]), "r"(a[3]), "r"(b[0]), "r"(b[1]));
}
__device__ __forceinline__ float gelu_exact(float x) {
    return 0.5f * x * (1.0f + erff(x * 0.7071067811865476f));
}
__device__ __forceinline__ uint32_t pack_hi_lo(float a, float b, uint32_t& lo) {
    __half h0 = __float2half_rn(a);
    __half h1 = __float2half_rn(b);
    float r0 = a - __half2float(h0);
    float r1 = b - __half2float(h1);
    __half l0 = __float2half_rn(r0);
    __half l1 = __float2half_rn(r1);
    lo = (uint32_t)__half_as_ushort(l0) | ((uint32_t)__half_as_ushort(l1) << 16);
    return (uint32_t)__half_as_ushort(h0) | ((uint32_t)__half_as_ushort(h1) << 16);
}

// ---------------------------------------------------------------------------
__global__ void quant_prep_kernel(const float* __restrict__ vw1,
                                  const float* __restrict__ vw2,
                                  const float* __restrict__ pw1,
                                  const float* __restrict__ pw2) {
    __shared__ float red[512];
    const float* W; int n; float* out;
    switch (blockIdx.x) {
        case 0:  W = vw1; n = 32;  out = d_q;       break;
        case 1:  W = vw2; n = 48;  out = d_q + 32;  break;
        case 2:  W = pw1; n = 288; out = d_q + 80;  break;
        default: W = pw2; n = 480; out = d_q + 368; break;
    }
    int t = threadIdx.x;
    red[t] = (t < n) ? fabsf(W[t]) : 0.0f;
    __syncthreads();
#pragma unroll
    for (int s = 256; s > 0; s >>= 1) {
        if (t < s) red[t] += red[t + s];
        __syncthreads();
    }
    float scale = red[0] / (float)n;
    if (t < n) {
        float q = rintf(W[t] / (scale + 1e-5f));
        q = fminf(fmaxf(q, -1.0f), 1.0f);
        out[t] = q * scale;
    }
}

// ---------------------------------------------------------------------------
__global__ void __launch_bounds__(THREADS, 1)
encoder_hmma_kernel(const int* __restrict__ read_count,
                    const int* __restrict__ write_count,
                    const int* __restrict__ fault_count,
                    const int* __restrict__ cow_count,
                    const int* __restrict__ recency,
                    const float* __restrict__ volatility,
                    const float* __restrict__ pressure,
                    const float* __restrict__ count_emb,
                    const float* __restrict__ recency_emb,
                    const float* __restrict__ p_b1,
                    const float* __restrict__ p_b2,
                    const float* __restrict__ v_b1,
                    const float* __restrict__ v_b2,
                    const float* __restrict__ f_wh,
                    const float* __restrict__ f_bh,
                    const float* __restrict__ f_wg,
                    const float* __restrict__ f_bg,
                    const float* __restrict__ ln_g,
                    const float* __restrict__ ln_b,
                    float* __restrict__ out,
                    int num_tiles) {
    extern __shared__ char smraw[];
    float* spar = (float*)(smraw + SM_PAR);
    const uint32_t sbase = smem_u32(smraw);
    const int tid = threadIdx.x;
    const int w   = tid >> 5;
    const int lid = tid & 31;
    const int rl  = lid;              // row within warp region

    // ---- build W hi/lo in smem (k-major, 1024B rows, 16B-chunk swizzle) ----
    for (int i = tid; i < 512 * 64; i += THREADS) {
        int n = i >> 6, k = i & 63;
        float wv = 0.0f;
        if (k < 51)       wv = (n < 256) ? f_wh[n * 51 + k] : f_wg[(n - 256) * 51 + k];
        else if (k == 51) wv = (n < 256) ? f_bh[n] : f_bg[n - 256];
        __half hi = __float2half_rn(wv);
        __half lo = __float2half_rn(wv - __half2float(hi));
        uint32_t off = (uint32_t)k * 1024u + ((((uint32_t)n >> 3) ^ ((uint32_t)k & 7)) << 4)
                       + (((uint32_t)n & 7) << 1);
        *(__half*)(smraw + SM_WH + off) = hi;
        *(__half*)(smraw + SM_WL + off) = lo;
    }
    // params
    for (int i = tid; i < 320; i += THREADS) {
        spar[P_CEMB + i] = count_emb[i];
        spar[P_REMB + i] = recency_emb[i];
    }
    for (int i = tid; i < 848; i += THREADS) spar[P_Q + i] = d_q[i];
    if (tid < 8)  spar[P_SB + tid]      = v_b1[tid];
    if (tid < 6)  spar[P_SB + 8 + tid]  = v_b2[tid];
    if (tid < 24) spar[P_SB + 16 + tid] = p_b1[tid];
    if (tid < 20) spar[P_SB + 40 + tid] = p_b2[tid];
    if (tid < 256) { spar[P_LNG + tid] = ln_g[tid]; spar[P_LNB + tid] = ln_b[tid]; }
    __syncthreads();

    const float* s_q  = spar + P_Q;
    const float* s_sb = spar + P_SB;
    const float2* lng2 = (const float2*)(spar + P_LNG);
    const float2* lnb2 = (const float2*)(spar + P_LNB);

    const uint32_t a_hi_base = sbase + SM_AH + (uint32_t)w * 4096u;
    const uint32_t a_lo_base = sbase + SM_AL + (uint32_t)w * 4096u;
    const uint32_t wh_base   = sbase + SM_WH;
    const uint32_t wl_base   = sbase + SM_WL;

    const int grp = lid >> 3, li = lid & 7;
    const int r0  = lid >> 2;           // 0..7 (row within 8-row half)
    const int cql = (lid & 3) << 1;     // 0,2,4,6 (col pair within chunk)

    // -------------------- persistent tile loop ------------------------------
    for (int t = blockIdx.x; t < num_tiles; t += gridDim.x) {
        const size_t rowbase = (size_t)t * ROWS_PER_CTA;
        const size_t myrow = rowbase + (size_t)tid;

        __syncwarp();  // guard previous iter's ldmatrix vs A overwrite

        // ---- phase 0: scalar front-end, one row per thread ---------------
        {
            float c[64];
#pragma unroll
            for (int k = 0; k < 64; k++) c[k] = 0.0f;
            c[51] = 1.0f;

            const int rc = read_count[myrow], wc = write_count[myrow];
            const int fc = fault_count[myrow], cc = cow_count[myrow];
            const int rr = recency[myrow];
#pragma unroll
            for (int d = 0; d < 5; d++) {
                c[d]      = spar[P_CEMB + rc * 5 + d];
                c[5 + d]  = spar[P_CEMB + wc * 5 + d];
                c[10 + d] = spar[P_CEMB + fc * 5 + d];
                c[15 + d] = spar[P_CEMB + cc * 5 + d];
                c[20 + d] = spar[P_REMB + rr * 5 + d];
            }
            float4 v4 = ((const float4*)volatility)[myrow];
            float va[4] = {v4.x, v4.y, v4.z, v4.w};
            float4 pA = ((const float4*)pressure)[myrow * 3 + 0];
            float4 pB = ((const float4*)pressure)[myrow * 3 + 1];
            float4 pC = ((const float4*)pressure)[myrow * 3 + 2];
            float pr[12] = {pA.x, pA.y, pA.z, pA.w, pB.x, pB.y, pB.z, pB.w,
                            pC.x, pC.y, pC.z, pC.w};
            float v1[8];
#pragma unroll
            for (int j = 0; j < 8; j++) {
                float a = s_sb[j];
#pragma unroll
                for (int i = 0; i < 4; i++) a = fmaf(s_q[j * 4 + i], va[i], a);
                v1[j] = gelu_exact(a);
            }
#pragma unroll
            for (int j = 0; j < 6; j++) {
                float a = s_sb[8 + j];
#pragma unroll
                for (int i = 0; i < 8; i++) a = fmaf(s_q[32 + j * 8 + i], v1[i], a);
                c[25 + j] = a;
            }
            float p1[24];
#pragma unroll
            for (int j = 0; j < 24; j++) {
                float a = s_sb[16 + j];
#pragma unroll
                for (int i = 0; i < 12; i++) a = fmaf(s_q[80 + j * 12 + i], pr[i], a);
                p1[j] = gelu_exact(a);
            }
#pragma unroll
            for (int j = 0; j < 20; j++) {
                float a = s_sb[40 + j];
#pragma unroll
                for (int i = 0; i < 24; i++) a = fmaf(s_q[368 + j * 24 + i], p1[i], a);
                c[31 + j] = a;
            }
            // write A hi/lo: 8 chunks of 16B, swizzled
            const uint32_t rbase = (uint32_t)rl * 128u;
#pragma unroll
            for (int j = 0; j < 8; j++) {
                uint32_t hw[4], lw[4];
#pragma unroll
                for (int q = 0; q < 4; q++)
                    hw[q] = pack_hi_lo(c[8 * j + 2 * q], c[8 * j + 2 * q + 1], lw[q]);
                uint32_t off = rbase + (((uint32_t)(j ^ (rl & 7))) << 4);
                *(uint4*)(smraw + SM_AH + (uint32_t)w * 4096u + off) =
                    make_uint4(hw[0], hw[1], hw[2], hw[3]);
                *(uint4*)(smraw + SM_AL + (uint32_t)w * 4096u + off) =
                    make_uint4(lw[0], lw[1], lw[2], lw[3]);
            }
        }
        __syncwarp();

        // ---- load A fragments (2 row-tiles x 4 k-steps) --------------------
        uint32_t Ahi[2][4][4], Alo[2][4][4];
#pragma unroll
        for (int rt = 0; rt < 2; rt++) {
#pragma unroll
            for (int ks = 0; ks < 4; ks++) {
                int rloc = rt * 16 + ((grp & 1) << 3) + li;
                int ch = 2 * ks + (grp >> 1);
                uint32_t off = (uint32_t)rloc * 128u
                               + (((uint32_t)(ch ^ (rloc & 7))) << 4);
                ldsm_x4(Ahi[rt][ks], a_hi_base + off);
                ldsm_x4(Alo[rt][ks], a_lo_base + off);
            }
        }

        // ---- main GEMM + epilogue pass 1 -----------------------------------
        float sum[4]  = {0.f, 0.f, 0.f, 0.f};
        float ssq[4]  = {0.f, 0.f, 0.f, 0.f};
        const size_t warp_row0 = rowbase + (size_t)w * ROWS_PER_WARP;

#pragma unroll 1
        for (int nc = 0; nc < NCHUNKS; nc++) {
            // B fragments: h (chunk nc), g (chunk nc+32), hi & lo
            uint32_t bhh[8], bhl[8], bgh[8], bgl[8];
#pragma unroll
            for (int kh = 0; kh < 2; kh++) {
                int krow = kh * 32 + grp * 8 + li;
                uint32_t rowoff = (uint32_t)krow * 1024u;
                uint32_t swh = (((uint32_t)(nc        ^ (krow & 7))) << 4);
                uint32_t swg = (((uint32_t)((nc + 32) ^ (krow & 7))) << 4);
                ldsm_x4t(&bhh[kh * 4], wh_base + rowoff + swh);
                ldsm_x4t(&bhl[kh * 4], wl_base + rowoff + swh);
                ldsm_x4t(&bgh[kh * 4], wh_base + rowoff + swg);
                ldsm_x4t(&bgl[kh * 4], wl_base + rowoff + swg);
            }
#pragma unroll
            for (int rt = 0; rt < 2; rt++) {
                float hacc[4] = {0.f, 0.f, 0.f, 0.f};
                float gacc[4] = {0.f, 0.f, 0.f, 0.f};
#pragma unroll
                for (int ks = 0; ks < 4; ks++) {
                    mma16816(hacc, Ahi[rt][ks], &bhh[2 * ks]);
                    mma16816(hacc, Alo[rt][ks], &bhh[2 * ks]);
                    mma16816(hacc, Ahi[rt][ks], &bhl[2 * ks]);
                    mma16816(gacc, Ahi[rt][ks], &bgh[2 * ks]);
                    mma16816(gacc, Alo[rt][ks], &bgh[2 * ks]);
                    mma16816(gacc, Ahi[rt][ks], &bgl[2 * ks]);
                }
                // z = h * sigmoid(g); store un-normalized; accumulate stats
                float z0 = hacc[0] / (1.0f + __expf(-gacc[0]));
                float z1 = hacc[1] / (1.0f + __expf(-gacc[1]));
                float z2 = hacc[2] / (1.0f + __expf(-gacc[2]));
                float z3 = hacc[3] / (1.0f + __expf(-gacc[3]));
                int col = nc * 8 + cql;
                size_t ra = warp_row0 + (size_t)(rt * 16 + r0);
                *(float2*)(out + ra * 256 + col)       = make_float2(z0, z1);
                *(float2*)(out + (ra + 8) * 256 + col) = make_float2(z2, z3);
                sum[rt * 2]     += z0 + z1;
                ssq[rt * 2]      = fmaf(z0, z0, fmaf(z1, z1, ssq[rt * 2]));
                sum[rt * 2 + 1] += z2 + z3;
                ssq[rt * 2 + 1]  = fmaf(z2, z2, fmaf(z3, z3, ssq[rt * 2 + 1]));
            }
        }

        // ---- row stats: reduce across the 4 lanes of each quad -------------
        float mu[4], rstd[4];
#pragma unroll
        for (int s = 0; s < 4; s++) {
            float a = sum[s], b = ssq[s];
            a += __shfl_xor_sync(0xffffffffu, a, 1);
            b += __shfl_xor_sync(0xffffffffu, b, 1);
            a += __shfl_xor_sync(0xffffffffu, a, 2);
            b += __shfl_xor_sync(0xffffffffu, b, 2);
            float m = a * (1.0f / 256.0f);
            float v = fmaxf(b * (1.0f / 256.0f) - m * m, 0.0f);
            mu[s] = m;
            rstd[s] = rsqrtf(v + 1e-5f);
        }

        // ---- pass 2: normalize (L2-hot readback) ---------------------------
#pragma unroll 1
        for (int nc = 0; nc < NCHUNKS; nc++) {
            int col = nc * 8 + cql;
            float2 lg = lng2[col >> 1];
            float2 lb = lnb2[col >> 1];
#pragma unroll
            for (int s = 0; s < 4; s++) {
                size_t r = warp_row0 + (size_t)((s >> 1) * 16 + (s & 1) * 8 + r0);
                float2 z = *(float2*)(out + r * 256 + col);
                z.x = fmaf((z.x - mu[s]) * rstd[s], lg.x, lb.x);
                z.y = fmaf((z.y - mu[s]) * rstd[s], lg.y, lb.y);
                *(float2*)(out + r * 256 + col) = z;
            }
        }
    }
}

// ---------------------------------------------------------------------------
extern "C" void kernel_launch(void* const* d_in, const int* in_sizes, int n_in,
                              void* d_out, int out_size) {
    const int* read_count  = (const int*)d_in[0];
    const int* write_count = (const int*)d_in[1];
    const int* fault_count = (const int*)d_in[2];
    const int* cow_count   = (const int*)d_in[3];
    const int* recency     = (const int*)d_in[4];
    const float* volatility  = (const float*)d_in[5];
    const float* pressure    = (const float*)d_in[6];
    const float* count_emb   = (const float*)d_in[7];
    const float* recency_emb = (const float*)d_in[8];
    const float* p_w1 = (const float*)d_in[9];
    const float* p_b1 = (const float*)d_in[10];
    const float* p_w2 = (const float*)d_in[11];
    const float* p_b2 = (const float*)d_in[12];
    const float* v_w1 = (const float*)d_in[13];
    const float* v_b1 = (const float*)d_in[14];
    const float* v_w2 = (const float*)d_in[15];
    const float* v_b2 = (const float*)d_in[16];
    const float* f_wh = (const float*)d_in[17];
    const float* f_bh = (const float*)d_in[18];
    const float* f_wg = (const float*)d_in[19];
    const float* f_bg = (const float*)d_in[20];
    const float* ln_g = (const float*)d_in[21];
    const float* ln_b = (const float*)d_in[22];
    float* out = (float*)d_out;

    const int B = in_sizes[0];
    const int num_tiles = B / ROWS_PER_CTA;  // 2048

    int dev = 0, sms = 148;
    cudaGetDevice(&dev);
    cudaDeviceGetAttribute(&sms, cudaDevAttrMultiProcessorCount, dev);
    int grid = num_tiles < sms ? num_tiles : sms;

    quant_prep_kernel<<<4, 512>>>(v_w1, v_w2, p_w1, p_w2);

    cudaFuncSetAttribute(encoder_hmma_kernel,
                         cudaFuncAttributeMaxDynamicSharedMemorySize, SMEM_BYTES);
    encoder_hmma_kernel<<<grid, THREADS, SMEM_BYTES>>>(
        read_count, write_count, fault_count, cow_count, recency,
        volatility, pressure, count_emb, recency_emb,
        p_b1, p_b2, v_b1, v_b2,
        f_wh, f_bh, f_wg, f_bg, ln_g, ln_b, out, num_tiles);
}

// round 4
// speedup vs baseline: 2.0871x; 1.1105x over previous
#include <cuda_runtime.h>
#include <cuda_fp16.h>
#include <cstdint>

// ===========================================================================
// BitNetSummaryEncoder — HMMA, register-resident B.
//   Warp w owns output cols [32w, 32w+32) (h and g) for ALL 256 rows/tile.
//   B fragments (hi+lo, h+g, k=64) loaded ONCE into 128 registers.
//   3-term fp16 split:  Ahi*Whi + Alo*Whi + Ahi*Wlo
//   z = h * sigmoid(g); LN via cross-warp smem reduce + L2-hot pass2.
// ===========================================================================

#define THREADS       256
#define ROWS_PER_CTA  256
#define MTILES        16

__device__ float d_q[848];    // quantized ternary weights

// ---------------- smem layout (bytes) --------------------------------------
#define SM_WH   0u            // W hi: 64 k x 512 n x 2B = 65536
#define SM_WL   65536u
#define SM_AH   131072u       // A hi: 256 rows x 128B = 32768
#define SM_AL   163840u
#define SM_RED  196608u       // 256 rows x 9 float2 (8 warps + pad) = 18432
#define SM_STAT 215040u       // 256 x float2 = 2048
#define SM_PAR  217088u       // params (float offsets below)
#define P_CEMB  0
#define P_REMB  320
#define P_Q     640
#define P_SB    1488
#define P_LNG   1552
#define P_LNB   1808
#define P_END   2064
#define SMEM_BYTES (SM_PAR + P_END * 4)

// ---------------- PTX helpers -----------------------------------------------
__device__ __forceinline__ uint32_t smem_u32(const void* p) {
    uint32_t a;
    asm("{ .reg .u64 t; cvta.to.shared.u64 t, %1; cvt.u32.u64 %0, t; }"
        : "=r"(a) : "l"(p));
    return a;
}
__device__ __forceinline__ void ldsm_x4(uint32_t* r, uint32_t addr) {
    asm volatile("ldmatrix.sync.aligned.m8n8.x4.shared.b16 {%0,%1,%2,%3}, [%4];"
                 : "=r"(r[0]), "=r"(r[1]), "=r"(r[2]), "=r"(r[3]) : "r"(addr));
}
__device__ __forceinline__ void ldsm_x4t(uint32_t* r, uint32_t addr) {
    asm volatile("ldmatrix.sync.aligned.m8n8.x4.trans.shared.b16 {%0,%1,%2,%3}, [%4];"
                 : "=r"(r[0]), "=r"(r[1]), "=r"(r[2]), "=r"(r[3]) : "r"(addr));
}
__device__ __forceinline__ void mma16816(float* d, const uint32_t* a,
                                         const uint32_t* b) {
    asm volatile(
        "mma.sync.aligned.m16n8k16.row.col.f32.f16.f16.f32 "
        "{%0,%1,%2,%3}, {%4,%5,%6,%7}, {%8,%9}, {%0,%1,%2,%3};"
        : "+f"(d[0]), "+f"(d[1]), "+f"(d[2]), "+f"(d[3])
        : "r"(a[0]), "r"(a[1]), "r"(a[2]), "r"(a[3]), "r"(b[0]), "r"(b[1]));
}
__device__ __forceinline__ float gelu_exact(float x) {
    return 0.5f * x * (1.0f + erff(x * 0.7071067811865476f));
}
__device__ __forceinline__ uint32_t pack_hi_lo(float a, float b, uint32_t& lo) {
    __half h0 = __float2half_rn(a);
    __half h1 = __float2half_rn(b);
    float r0 = a - __half2float(h0);
    float r1 = b - __half2float(h1);
    __half l0 = __float2half_rn(r0);
    __half l1 = __float2half_rn(r1);
    lo = (uint32_t)__half_as_ushort(l0) | ((uint32_t)__half_as_ushort(l1) << 16);
    return (uint32_t)__half_as_ushort(h0) | ((uint32_t)__half_as_ushort(h1) << 16);
}

// ---------------------------------------------------------------------------
__global__ void quant_prep_kernel(const float* __restrict__ vw1,
                                  const float* __restrict__ vw2,
                                  const float* __restrict__ pw1,
                                  const float* __restrict__ pw2) {
    __shared__ float red[512];
    const float* W; int n; float* out;
    switch (blockIdx.x) {
        case 0:  W = vw1; n = 32;  out = d_q;       break;
        case 1:  W = vw2; n = 48;  out = d_q + 32;  break;
        case 2:  W = pw1; n = 288; out = d_q + 80;  break;
        default: W = pw2; n = 480; out = d_q + 368; break;
    }
    int t = threadIdx.x;
    red[t] = (t < n) ? fabsf(W[t]) : 0.0f;
    __syncthreads();
#pragma unroll
    for (int s = 256; s > 0; s >>= 1) {
        if (t < s) red[t] += red[t + s];
        __syncthreads();
    }
    float scale = red[0] / (float)n;
    if (t < n) {
        float q = rintf(W[t] / (scale + 1e-5f));
        q = fminf(fmaxf(q, -1.0f), 1.0f);
        out[t] = q * scale;
    }
}

// ---------------------------------------------------------------------------
__global__ void __launch_bounds__(THREADS, 1)
encoder_hmma_kernel(const int* __restrict__ read_count,
                    const int* __restrict__ write_count,
                    const int* __restrict__ fault_count,
                    const int* __restrict__ cow_count,
                    const int* __restrict__ recency,
                    const float* __restrict__ volatility,
                    const float* __restrict__ pressure,
                    const float* __restrict__ count_emb,
                    const float* __restrict__ recency_emb,
                    const float* __restrict__ p_b1,
                    const float* __restrict__ p_b2,
                    const float* __restrict__ v_b1,
                    const float* __restrict__ v_b2,
                    const float* __restrict__ f_wh,
                    const float* __restrict__ f_bh,
                    const float* __restrict__ f_wg,
                    const float* __restrict__ f_bg,
                    const float* __restrict__ ln_g,
                    const float* __restrict__ ln_b,
                    float* __restrict__ out,
                    int num_tiles) {
    extern __shared__ char smraw[];
    float* spar = (float*)(smraw + SM_PAR);
    const uint32_t sbase = smem_u32(smraw);
    const int tid = threadIdx.x;
    const int w   = tid >> 5;
    const int lid = tid & 31;

    // ---- build W hi/lo in smem (k-major, 1024B rows, 16B-chunk swizzle) ----
    for (int i = tid; i < 512 * 64; i += THREADS) {
        int n = i >> 6, k = i & 63;
        float wv = 0.0f;
        if (k < 51)       wv = (n < 256) ? f_wh[n * 51 + k] : f_wg[(n - 256) * 51 + k];
        else if (k == 51) wv = (n < 256) ? f_bh[n] : f_bg[n - 256];
        __half hi = __float2half_rn(wv);
        __half lo = __float2half_rn(wv - __half2float(hi));
        uint32_t off = (uint32_t)k * 1024u + ((((uint32_t)n >> 3) ^ ((uint32_t)k & 7)) << 4)
                       + (((uint32_t)n & 7) << 1);
        *(__half*)(smraw + SM_WH + off) = hi;
        *(__half*)(smraw + SM_WL + off) = lo;
    }
    for (int i = tid; i < 320; i += THREADS) {
        spar[P_CEMB + i] = count_emb[i];
        spar[P_REMB + i] = recency_emb[i];
    }
    for (int i = tid; i < 848; i += THREADS) spar[P_Q + i] = d_q[i];
    if (tid < 8)  spar[P_SB + tid]      = v_b1[tid];
    if (tid < 6)  spar[P_SB + 8 + tid]  = v_b2[tid];
    if (tid < 24) spar[P_SB + 16 + tid] = p_b1[tid];
    if (tid < 20) spar[P_SB + 40 + tid] = p_b2[tid];
    if (tid < 256) { spar[P_LNG + tid] = ln_g[tid]; spar[P_LNB + tid] = ln_b[tid]; }
    __syncthreads();

    const float* s_q  = spar + P_Q;
    const float* s_sb = spar + P_SB;

    const uint32_t a_hi_base = sbase + SM_AH;
    const uint32_t a_lo_base = sbase + SM_AL;
    const uint32_t wh_base   = sbase + SM_WH;
    const uint32_t wl_base   = sbase + SM_WL;
    float2* red2  = (float2*)(smraw + SM_RED);
    float2* stat2 = (float2*)(smraw + SM_STAT);

    const int grp = lid >> 3, li = lid & 7;
    const int r0  = lid >> 2;           // 0..7
    const int cql = (lid & 3) << 1;     // 0,2,4,6

    // ---- load register-resident B fragments (once per kernel) --------------
    // chunks 0..3: h cols [32w..32w+32); chunks 4..7: g cols (same, +256)
    uint32_t Bhi[8][8], Blo[8][8];
#pragma unroll
    for (int c = 0; c < 4; c++) {
        const int chh = w * 4 + c;
        const int chg = 32 + w * 4 + c;
#pragma unroll
        for (int kh = 0; kh < 2; kh++) {
            int krow = kh * 32 + grp * 8 + li;
            uint32_t rowoff = (uint32_t)krow * 1024u;
            uint32_t swh = (((uint32_t)(chh ^ (krow & 7))) << 4);
            uint32_t swg = (((uint32_t)(chg ^ (krow & 7))) << 4);
            ldsm_x4t(&Bhi[c][kh * 4],     wh_base + rowoff + swh);
            ldsm_x4t(&Blo[c][kh * 4],     wl_base + rowoff + swh);
            ldsm_x4t(&Bhi[4 + c][kh * 4], wh_base + rowoff + swg);
            ldsm_x4t(&Blo[4 + c][kh * 4], wl_base + rowoff + swg);
        }
    }

    // -------------------- persistent tile loop ------------------------------
    for (int t = blockIdx.x; t < num_tiles; t += gridDim.x) {
        const size_t rowbase = (size_t)t * ROWS_PER_CTA;
        const size_t myrow = rowbase + (size_t)tid;

        // ---- phase 0: scalar front-end, one row per thread -> A smem ------
        {
            float c[64];
#pragma unroll
            for (int k = 0; k < 64; k++) c[k] = 0.0f;
            c[51] = 1.0f;

            const int rc = read_count[myrow], wc = write_count[myrow];
            const int fc = fault_count[myrow], cc = cow_count[myrow];
            const int rr = recency[myrow];
#pragma unroll
            for (int d = 0; d < 5; d++) {
                c[d]      = spar[P_CEMB + rc * 5 + d];
                c[5 + d]  = spar[P_CEMB + wc * 5 + d];
                c[10 + d] = spar[P_CEMB + fc * 5 + d];
                c[15 + d] = spar[P_CEMB + cc * 5 + d];
                c[20 + d] = spar[P_REMB + rr * 5 + d];
            }
            float4 v4 = ((const float4*)volatility)[myrow];
            float va[4] = {v4.x, v4.y, v4.z, v4.w};
            float4 pA = ((const float4*)pressure)[myrow * 3 + 0];
            float4 pB = ((const float4*)pressure)[myrow * 3 + 1];
            float4 pC = ((const float4*)pressure)[myrow * 3 + 2];
            float pr[12] = {pA.x, pA.y, pA.z, pA.w, pB.x, pB.y, pB.z, pB.w,
                            pC.x, pC.y, pC.z, pC.w};
            float v1[8];
#pragma unroll
            for (int j = 0; j < 8; j++) {
                float a = s_sb[j];
#pragma unroll
                for (int i = 0; i < 4; i++) a = fmaf(s_q[j * 4 + i], va[i], a);
                v1[j] = gelu_exact(a);
            }
#pragma unroll
            for (int j = 0; j < 6; j++) {
                float a = s_sb[8 + j];
#pragma unroll
                for (int i = 0; i < 8; i++) a = fmaf(s_q[32 + j * 8 + i], v1[i], a);
                c[25 + j] = a;
            }
            float p1[24];
#pragma unroll
            for (int j = 0; j < 24; j++) {
                float a = s_sb[16 + j];
#pragma unroll
                for (int i = 0; i < 12; i++) a = fmaf(s_q[80 + j * 12 + i], pr[i], a);
                p1[j] = gelu_exact(a);
            }
#pragma unroll
            for (int j = 0; j < 20; j++) {
                float a = s_sb[40 + j];
#pragma unroll
                for (int i = 0; i < 24; i++) a = fmaf(s_q[368 + j * 24 + i], p1[i], a);
                c[31 + j] = a;
            }
            const uint32_t rbase = (uint32_t)tid * 128u;
#pragma unroll
            for (int j = 0; j < 8; j++) {
                uint32_t hw[4], lw[4];
#pragma unroll
                for (int q = 0; q < 4; q++)
                    hw[q] = pack_hi_lo(c[8 * j + 2 * q], c[8 * j + 2 * q + 1], lw[q]);
                uint32_t off = rbase + (((uint32_t)(j ^ (tid & 7))) << 4);
                *(uint4*)(smraw + SM_AH + off) = make_uint4(hw[0], hw[1], hw[2], hw[3]);
                *(uint4*)(smraw + SM_AL + off) = make_uint4(lw[0], lw[1], lw[2], lw[3]);
            }
        }
        __syncthreads();   // A ready

        // ---- GEMM: 16 m-tiles x (4 h-chunks + 4 g-chunks) ------------------
#pragma unroll 1
        for (int mt = 0; mt < MTILES; mt++) {
            uint32_t Ahi[4][4], Alo[4][4];
            const int rloc = mt * 16 + ((grp & 1) << 3) + li;
            const uint32_t roff = (uint32_t)rloc * 128u;
#pragma unroll
            for (int ks = 0; ks < 4; ks++) {
                const int ch = 2 * ks + (grp >> 1);
                const uint32_t off = roff + (((uint32_t)(ch ^ (rloc & 7))) << 4);
                ldsm_x4(Ahi[ks], a_hi_base + off);
                ldsm_x4(Alo[ks], a_lo_base + off);
            }
            float acc[8][4];
#pragma unroll
            for (int c = 0; c < 8; c++)
#pragma unroll
                for (int i = 0; i < 4; i++) acc[c][i] = 0.0f;
#pragma unroll
            for (int ks = 0; ks < 4; ks++) {
#pragma unroll
                for (int c = 0; c < 8; c++) {
                    mma16816(acc[c], Ahi[ks], &Bhi[c][2 * ks]);
                    mma16816(acc[c], Alo[ks], &Bhi[c][2 * ks]);
                    mma16816(acc[c], Ahi[ks], &Blo[c][2 * ks]);
                }
            }
            // ---- z = h*sigmoid(g), store, per-lane partial stats ----------
            float s0 = 0.f, q0 = 0.f, s8 = 0.f, q8 = 0.f;
            const size_t ra = rowbase + (size_t)(mt * 16 + r0);
#pragma unroll
            for (int c = 0; c < 4; c++) {
                float z0 = acc[c][0] / (1.0f + __expf(-acc[4 + c][0]));
                float z1 = acc[c][1] / (1.0f + __expf(-acc[4 + c][1]));
                float z2 = acc[c][2] / (1.0f + __expf(-acc[4 + c][2]));
                float z3 = acc[c][3] / (1.0f + __expf(-acc[4 + c][3]));
                const int col = w * 32 + c * 8 + cql;
                *(float2*)(out + ra * 256 + col)       = make_float2(z0, z1);
                *(float2*)(out + (ra + 8) * 256 + col) = make_float2(z2, z3);
                s0 += z0 + z1;
                q0 = fmaf(z0, z0, fmaf(z1, z1, q0));
                s8 += z2 + z3;
                q8 = fmaf(z2, z2, fmaf(z3, z3, q8));
            }
            // quad reduce (cols)
            s0 += __shfl_xor_sync(0xffffffffu, s0, 1);
            q0 += __shfl_xor_sync(0xffffffffu, q0, 1);
            s8 += __shfl_xor_sync(0xffffffffu, s8, 1);
            q8 += __shfl_xor_sync(0xffffffffu, q8, 1);
            s0 += __shfl_xor_sync(0xffffffffu, s0, 2);
            q0 += __shfl_xor_sync(0xffffffffu, q0, 2);
            s8 += __shfl_xor_sync(0xffffffffu, s8, 2);
            q8 += __shfl_xor_sync(0xffffffffu, q8, 2);
            if ((lid & 3) == 0) {
                red2[(mt * 16 + r0) * 9 + w]     = make_float2(s0, q0);
                red2[(mt * 16 + 8 + r0) * 9 + w] = make_float2(s8, q8);
            }
        }
        __syncthreads();   // red ready (also orders pass-1 global stores)

        // ---- per-row stats ----------------------------------------------
        {
            float s = 0.f, q = 0.f;
#pragma unroll
            for (int k = 0; k < 8; k++) {
                float2 p = red2[tid * 9 + k];
                s += p.x;
                q += p.y;
            }
            float mu = s * (1.0f / 256.0f);
            float var = fmaxf(q * (1.0f / 256.0f) - mu * mu, 0.0f);
            stat2[tid] = make_float2(mu, rsqrtf(var + 1e-5f));
        }
        __syncthreads();   // stats ready

        // ---- pass 2: normalize (L2-hot) -----------------------------------
        {
            const float4* lng4 = (const float4*)(spar + P_LNG);
            const float4* lnb4 = (const float4*)(spar + P_LNB);
            float4* out4 = (float4*)(out + rowbase * 256);
#pragma unroll 4
            for (int i = tid; i < ROWS_PER_CTA * 64; i += THREADS) {
                const int r = i >> 6, c4 = i & 63;
                float4 z = out4[i];
                float2 st = stat2[r];
                float4 gg = lng4[c4];
                float4 bb = lnb4[c4];
                z.x = fmaf((z.x - st.x) * st.y, gg.x, bb.x);
                z.y = fmaf((z.y - st.x) * st.y, gg.y, bb.y);
                z.z = fmaf((z.z - st.x) * st.y, gg.z, bb.z);
                z.w = fmaf((z.w - st.x) * st.y, gg.w, bb.w);
                out4[i] = z;
            }
        }
    }
}

// ---------------------------------------------------------------------------
extern "C" void kernel_launch(void* const* d_in, const int* in_sizes, int n_in,
                              void* d_out, int out_size) {
    const int* read_count  = (const int*)d_in[0];
    const int* write_count = (const int*)d_in[1];
    const int* fault_count = (const int*)d_in[2];
    const int* cow_count   = (const int*)d_in[3];
    const int* recency     = (const int*)d_in[4];
    const float* volatility  = (const float*)d_in[5];
    const float* pressure    = (const float*)d_in[6];
    const float* count_emb   = (const float*)d_in[7];
    const float* recency_emb = (const float*)d_in[8];
    const float* p_w1 = (const float*)d_in[9];
    const float* p_b1 = (const float*)d_in[10];
    const float* p_w2 = (const float*)d_in[11];
    const float* p_b2 = (const float*)d_in[12];
    const float* v_w1 = (const float*)d_in[13];
    const float* v_b1 = (const float*)d_in[14];
    const float* v_w2 = (const float*)d_in[15];
    const float* v_b2 = (const float*)d_in[16];
    const float* f_wh = (const float*)d_in[17];
    const float* f_bh = (const float*)d_in[18];
    const float* f_wg = (const float*)d_in[19];
    const float* f_bg = (const float*)d_in[20];
    const float* ln_g = (const float*)d_in[21];
    const float* ln_b = (const float*)d_in[22];
    float* out = (float*)d_out;

    const int B = in_sizes[0];
    const int num_tiles = B / ROWS_PER_CTA;  // 2048

    int dev = 0, sms = 148;
    cudaGetDevice(&dev);
    cudaDeviceGetAttribute(&sms, cudaDevAttrMultiProcessorCount, dev);
    int grid = num_tiles < sms ? num_tiles : sms;

    quant_prep_kernel<<<4, 512>>>(v_w1, v_w2, p_w1, p_w2);

    cudaFuncSetAttribute(encoder_hmma_kernel,
                         cudaFuncAttributeMaxDynamicSharedMemorySize, SMEM_BYTES);
    encoder_hmma_kernel<<<grid, THREADS, SMEM_BYTES>>>(
        read_count, write_count, fault_count, cow_count, recency,
        volatility, pressure, count_emb, recency_emb,
        p_b1, p_b2, v_b1, v_b2,
        f_wh, f_bh, f_wg, f_bg, ln_g, ln_b, out, num_tiles);
}

// round 5
// speedup vs baseline: 2.5459x; 1.2198x over previous
#include <cuda_runtime.h>
#include <cuda_fp16.h>
#include <cstdint>

// ===========================================================================
// BitNetSummaryEncoder — HMMA, register-resident B, 512 threads / 512-row tile.
//   Warp w owns output cols [16w, 16w+16) (h and g) for ALL 512 rows/tile.
//   B fragments (hi+lo, h+g, k=64) loaded ONCE into 64 registers/thread.
//   After B-frag load, W smem region is reused as the A (hi/lo) buffer.
//   3-term fp16 split:  Ahi*Whi + Alo*Whi + Ahi*Wlo
//   z = h * sigmoid(g); LN via cross-warp smem reduce + L2-hot pass2.
// ===========================================================================

#define THREADS       512
#define ROWS_PER_CTA  512
#define MTILES        32

__device__ float d_q[848];    // quantized ternary weights

// ---------------- smem layout (bytes) --------------------------------------
// init:   [0,65536) W hi   [65536,131072) W lo
// main:   [0,65536) A hi   [65536,131072) A lo      (W region reused)
#define SM_WH   0u
#define SM_WL   65536u
#define SM_AH   0u
#define SM_AL   65536u
#define SM_RED  131072u       // 512 rows x 17 float2 = 69632
#define SM_STAT 200704u       // 512 x float2 = 4096
#define SM_PAR  204800u       // params (float offsets below)
#define P_CEMB  0
#define P_REMB  320
#define P_Q     640
#define P_SB    1488
#define P_LNG   1552
#define P_LNB   1808
#define P_END   2064
#define SMEM_BYTES (SM_PAR + P_END * 4)   // 213056

// ---------------- PTX helpers -----------------------------------------------
__device__ __forceinline__ uint32_t smem_u32(const void* p) {
    uint32_t a;
    asm("{ .reg .u64 t; cvta.to.shared.u64 t, %1; cvt.u32.u64 %0, t; }"
        : "=r"(a) : "l"(p));
    return a;
}
__device__ __forceinline__ void ldsm_x4(uint32_t* r, uint32_t addr) {
    asm volatile("ldmatrix.sync.aligned.m8n8.x4.shared.b16 {%0,%1,%2,%3}, [%4];"
                 : "=r"(r[0]), "=r"(r[1]), "=r"(r[2]), "=r"(r[3]) : "r"(addr));
}
__device__ __forceinline__ void ldsm_x4t(uint32_t* r, uint32_t addr) {
    asm volatile("ldmatrix.sync.aligned.m8n8.x4.trans.shared.b16 {%0,%1,%2,%3}, [%4];"
                 : "=r"(r[0]), "=r"(r[1]), "=r"(r[2]), "=r"(r[3]) : "r"(addr));
}
__device__ __forceinline__ void mma16816(float* d, const uint32_t* a,
                                         const uint32_t* b) {
    asm volatile(
        "mma.sync.aligned.m16n8k16.row.col.f32.f16.f16.f32 "
        "{%0,%1,%2,%3}, {%4,%5,%6,%7}, {%8,%9}, {%0,%1,%2,%3};"
        : "+f"(d[0]), "+f"(d[1]), "+f"(d[2]), "+f"(d[3])
        : "r"(a[0]), "r"(a[1]), "r"(a[2]), "r"(a[3]), "r"(b[0]), "r"(b[1]));
}
__device__ __forceinline__ float gelu_exact(float x) {
    return 0.5f * x * (1.0f + erff(x * 0.7071067811865476f));
}
__device__ __forceinline__ uint32_t pack_hi_lo(float a, float b, uint32_t& lo) {
    __half h0 = __float2half_rn(a);
    __half h1 = __float2half_rn(b);
    float r0 = a - __half2float(h0);
    float r1 = b - __half2float(h1);
    __half l0 = __float2half_rn(r0);
    __half l1 = __float2half_rn(r1);
    lo = (uint32_t)__half_as_ushort(l0) | ((uint32_t)__half_as_ushort(l1) << 16);
    return (uint32_t)__half_as_ushort(h0) | ((uint32_t)__half_as_ushort(h1) << 16);
}

// ---------------------------------------------------------------------------
__global__ void quant_prep_kernel(const float* __restrict__ vw1,
                                  const float* __restrict__ vw2,
                                  const float* __restrict__ pw1,
                                  const float* __restrict__ pw2) {
    __shared__ float red[512];
    const float* W; int n; float* out;
    switch (blockIdx.x) {
        case 0:  W = vw1; n = 32;  out = d_q;       break;
        case 1:  W = vw2; n = 48;  out = d_q + 32;  break;
        case 2:  W = pw1; n = 288; out = d_q + 80;  break;
        default: W = pw2; n = 480; out = d_q + 368; break;
    }
    int t = threadIdx.x;
    red[t] = (t < n) ? fabsf(W[t]) : 0.0f;
    __syncthreads();
#pragma unroll
    for (int s = 256; s > 0; s >>= 1) {
        if (t < s) red[t] += red[t + s];
        __syncthreads();
    }
    float scale = red[0] / (float)n;
    if (t < n) {
        float q = rintf(W[t] / (scale + 1e-5f));
        q = fminf(fmaxf(q, -1.0f), 1.0f);
        out[t] = q * scale;
    }
}

// ---------------------------------------------------------------------------
__global__ void __launch_bounds__(THREADS, 1)
encoder_hmma_kernel(const int* __restrict__ read_count,
                    const int* __restrict__ write_count,
                    const int* __restrict__ fault_count,
                    const int* __restrict__ cow_count,
                    const int* __restrict__ recency,
                    const float* __restrict__ volatility,
                    const float* __restrict__ pressure,
                    const float* __restrict__ count_emb,
                    const float* __restrict__ recency_emb,
                    const float* __restrict__ p_b1,
                    const float* __restrict__ p_b2,
                    const float* __restrict__ v_b1,
                    const float* __restrict__ v_b2,
                    const float* __restrict__ f_wh,
                    const float* __restrict__ f_bh,
                    const float* __restrict__ f_wg,
                    const float* __restrict__ f_bg,
                    const float* __restrict__ ln_g,
                    const float* __restrict__ ln_b,
                    float* __restrict__ out,
                    int num_tiles) {
    extern __shared__ char smraw[];
    float* spar = (float*)(smraw + SM_PAR);
    const uint32_t sbase = smem_u32(smraw);
    const int tid = threadIdx.x;
    const int w   = tid >> 5;
    const int lid = tid & 31;

    // ---- build W hi/lo in smem (k-major, 1024B rows, 16B-chunk swizzle) ----
    for (int i = tid; i < 512 * 64; i += THREADS) {
        int n = i >> 6, k = i & 63;
        float wv = 0.0f;
        if (k < 51)       wv = (n < 256) ? f_wh[n * 51 + k] : f_wg[(n - 256) * 51 + k];
        else if (k == 51) wv = (n < 256) ? f_bh[n] : f_bg[n - 256];
        __half hi = __float2half_rn(wv);
        __half lo = __float2half_rn(wv - __half2float(hi));
        uint32_t off = (uint32_t)k * 1024u + ((((uint32_t)n >> 3) ^ ((uint32_t)k & 7)) << 4)
                       + (((uint32_t)n & 7) << 1);
        *(__half*)(smraw + SM_WH + off) = hi;
        *(__half*)(smraw + SM_WL + off) = lo;
    }
    for (int i = tid; i < 320; i += THREADS) {
        spar[P_CEMB + i] = count_emb[i];
        spar[P_REMB + i] = recency_emb[i];
    }
    for (int i = tid; i < 848; i += THREADS) spar[P_Q + i] = d_q[i];
    if (tid < 8)  spar[P_SB + tid]      = v_b1[tid];
    if (tid < 6)  spar[P_SB + 8 + tid]  = v_b2[tid];
    if (tid < 24) spar[P_SB + 16 + tid] = p_b1[tid];
    if (tid < 20) spar[P_SB + 40 + tid] = p_b2[tid];
    if (tid < 256) { spar[P_LNG + tid] = ln_g[tid]; spar[P_LNB + tid] = ln_b[tid]; }
    __syncthreads();

    const float* s_q  = spar + P_Q;
    const float* s_sb = spar + P_SB;

    float2* red2  = (float2*)(smraw + SM_RED);
    float2* stat2 = (float2*)(smraw + SM_STAT);

    const int grp = lid >> 3, li = lid & 7;
    const int r0  = lid >> 2;           // 0..7
    const int cql = (lid & 3) << 1;     // 0,2,4,6

    // ---- load register-resident B fragments (once) --------------------------
    // c 0..1: h chunks (global w*2+c); c 2..3: g chunks (32 + w*2 + c-2)
    uint32_t Bhi[4][8], Blo[4][8];
#pragma unroll
    for (int c = 0; c < 2; c++) {
        const int chh = w * 2 + c;
        const int chg = 32 + w * 2 + c;
#pragma unroll
        for (int kh = 0; kh < 2; kh++) {
            int krow = kh * 32 + grp * 8 + li;
            uint32_t rowoff = (uint32_t)krow * 1024u;
            uint32_t swh = (((uint32_t)(chh ^ (krow & 7))) << 4);
            uint32_t swg = (((uint32_t)(chg ^ (krow & 7))) << 4);
            ldsm_x4t(&Bhi[c][kh * 4],     sbase + SM_WH + rowoff + swh);
            ldsm_x4t(&Blo[c][kh * 4],     sbase + SM_WL + rowoff + swh);
            ldsm_x4t(&Bhi[2 + c][kh * 4], sbase + SM_WH + rowoff + swg);
            ldsm_x4t(&Blo[2 + c][kh * 4], sbase + SM_WL + rowoff + swg);
        }
    }
    __syncthreads();   // B frags read; W region may now be reused as A

    // per-thread A chunk writer: 8 values -> hi/lo uint4, swizzled
    const uint32_t a_rbase = (uint32_t)tid * 128u;
    auto store_chunk = [&](int j, const float* v8) {
        uint32_t hw[4], lw[4];
#pragma unroll
        for (int q = 0; q < 4; q++)
            hw[q] = pack_hi_lo(v8[2 * q], v8[2 * q + 1], lw[q]);
        uint32_t off = a_rbase + (((uint32_t)(j ^ (tid & 7))) << 4);
        *(uint4*)(smraw + SM_AH + off) = make_uint4(hw[0], hw[1], hw[2], hw[3]);
        *(uint4*)(smraw + SM_AL + off) = make_uint4(lw[0], lw[1], lw[2], lw[3]);
    };

    // -------------------- persistent tile loop ------------------------------
    for (int t = blockIdx.x; t < num_tiles; t += gridDim.x) {
        const size_t rowbase = (size_t)t * ROWS_PER_CTA;
        const size_t myrow = rowbase + (size_t)tid;

        // ---- phase 0: scalar front-end (streamed chunks -> A smem) ---------
        {
            const int rc = read_count[myrow], wc = write_count[myrow];
            const int fc = fault_count[myrow], cc = cow_count[myrow];
            const int rr = recency[myrow];
            float v8[8];
            // chunk 0: cemb[rc][0..4], cemb[wc][0..2]
#pragma unroll
            for (int d = 0; d < 5; d++) v8[d] = spar[P_CEMB + rc * 5 + d];
#pragma unroll
            for (int d = 0; d < 3; d++) v8[5 + d] = spar[P_CEMB + wc * 5 + d];
            store_chunk(0, v8);
            // chunk 1: cemb[wc][3,4], cemb[fc][0..4], cemb[cc][0]
            v8[0] = spar[P_CEMB + wc * 5 + 3];
            v8[1] = spar[P_CEMB + wc * 5 + 4];
#pragma unroll
            for (int d = 0; d < 5; d++) v8[2 + d] = spar[P_CEMB + fc * 5 + d];
            v8[7] = spar[P_CEMB + cc * 5 + 0];
            store_chunk(1, v8);
            // chunk 2: cemb[cc][1..4], remb[rr][0..3]
#pragma unroll
            for (int d = 0; d < 4; d++) v8[d] = spar[P_CEMB + cc * 5 + 1 + d];
#pragma unroll
            for (int d = 0; d < 4; d++) v8[4 + d] = spar[P_REMB + rr * 5 + d];
            store_chunk(2, v8);

            // small MLPs
            float4 v4 = ((const float4*)volatility)[myrow];
            float va[4] = {v4.x, v4.y, v4.z, v4.w};
            float v1[8];
#pragma unroll
            for (int j = 0; j < 8; j++) {
                float a = s_sb[j];
#pragma unroll
                for (int i = 0; i < 4; i++) a = fmaf(s_q[j * 4 + i], va[i], a);
                v1[j] = gelu_exact(a);
            }
            float pv[6];
#pragma unroll
            for (int j = 0; j < 6; j++) {
                float a = s_sb[8 + j];
#pragma unroll
                for (int i = 0; i < 8; i++) a = fmaf(s_q[32 + j * 8 + i], v1[i], a);
                pv[j] = a;
            }
            float4 pA = ((const float4*)pressure)[myrow * 3 + 0];
            float4 pB = ((const float4*)pressure)[myrow * 3 + 1];
            float4 pC = ((const float4*)pressure)[myrow * 3 + 2];
            float pr[12] = {pA.x, pA.y, pA.z, pA.w, pB.x, pB.y, pB.z, pB.w,
                            pC.x, pC.y, pC.z, pC.w};
            float p1[24];
#pragma unroll
            for (int j = 0; j < 24; j++) {
                float a = s_sb[16 + j];
#pragma unroll
                for (int i = 0; i < 12; i++) a = fmaf(s_q[80 + j * 12 + i], pr[i], a);
                p1[j] = gelu_exact(a);
            }
            auto pp = [&](int j) {
                float a = s_sb[40 + j];
#pragma unroll
                for (int i = 0; i < 24; i++) a = fmaf(s_q[368 + j * 24 + i], p1[i], a);
                return a;
            };
            // chunk 3: remb[rr][4], pv[0..5], pp(0)
            v8[0] = spar[P_REMB + rr * 5 + 4];
#pragma unroll
            for (int d = 0; d < 6; d++) v8[1 + d] = pv[d];
            v8[7] = pp(0);
            store_chunk(3, v8);
            // chunk 4: pp(1..8)
#pragma unroll
            for (int d = 0; d < 8; d++) v8[d] = pp(1 + d);
            store_chunk(4, v8);
            // chunk 5: pp(9..16)
#pragma unroll
            for (int d = 0; d < 8; d++) v8[d] = pp(9 + d);
            store_chunk(5, v8);
            // chunk 6: pp(17..19), bias 1.0, zeros
            v8[0] = pp(17); v8[1] = pp(18); v8[2] = pp(19);
            v8[3] = 1.0f; v8[4] = 0.f; v8[5] = 0.f; v8[6] = 0.f; v8[7] = 0.f;
            store_chunk(6, v8);
            // chunk 7: zeros
#pragma unroll
            for (int d = 0; d < 8; d++) v8[d] = 0.f;
            store_chunk(7, v8);
        }
        __syncthreads();   // A ready

        // ---- GEMM: 32 m-tiles x (2 h-chunks + 2 g-chunks) ------------------
#pragma unroll 1
        for (int mt = 0; mt < MTILES; mt++) {
            float acc[4][4];
#pragma unroll
            for (int c = 0; c < 4; c++)
#pragma unroll
                for (int i = 0; i < 4; i++) acc[c][i] = 0.0f;

            const int rloc = mt * 16 + ((grp & 1) << 3) + li;
            const uint32_t roff = (uint32_t)rloc * 128u;
#pragma unroll
            for (int ks = 0; ks < 4; ks++) {
                uint32_t Ahi[4], Alo[4];
                const int ch = 2 * ks + (grp >> 1);
                const uint32_t off = roff + (((uint32_t)(ch ^ (rloc & 7))) << 4);
                ldsm_x4(Ahi, sbase + SM_AH + off);
                ldsm_x4(Alo, sbase + SM_AL + off);
#pragma unroll
                for (int c = 0; c < 4; c++) {
                    mma16816(acc[c], Ahi, &Bhi[c][2 * ks]);
                    mma16816(acc[c], Alo, &Bhi[c][2 * ks]);
                    mma16816(acc[c], Ahi, &Blo[c][2 * ks]);
                }
            }
            // ---- z = h*sigmoid(g), store, per-lane partial stats ----------
            float s0 = 0.f, q0 = 0.f, s8 = 0.f, q8 = 0.f;
            const size_t ra = rowbase + (size_t)(mt * 16 + r0);
#pragma unroll
            for (int c = 0; c < 2; c++) {
                float z0 = acc[c][0] / (1.0f + __expf(-acc[2 + c][0]));
                float z1 = acc[c][1] / (1.0f + __expf(-acc[2 + c][1]));
                float z2 = acc[c][2] / (1.0f + __expf(-acc[2 + c][2]));
                float z3 = acc[c][3] / (1.0f + __expf(-acc[2 + c][3]));
                const int col = w * 16 + c * 8 + cql;
                *(float2*)(out + ra * 256 + col)       = make_float2(z0, z1);
                *(float2*)(out + (ra + 8) * 256 + col) = make_float2(z2, z3);
                s0 += z0 + z1;
                q0 = fmaf(z0, z0, fmaf(z1, z1, q0));
                s8 += z2 + z3;
                q8 = fmaf(z2, z2, fmaf(z3, z3, q8));
            }
            s0 += __shfl_xor_sync(0xffffffffu, s0, 1);
            q0 += __shfl_xor_sync(0xffffffffu, q0, 1);
            s8 += __shfl_xor_sync(0xffffffffu, s8, 1);
            q8 += __shfl_xor_sync(0xffffffffu, q8, 1);
            s0 += __shfl_xor_sync(0xffffffffu, s0, 2);
            q0 += __shfl_xor_sync(0xffffffffu, q0, 2);
            s8 += __shfl_xor_sync(0xffffffffu, s8, 2);
            q8 += __shfl_xor_sync(0xffffffffu, q8, 2);
            if ((lid & 3) == 0) {
                red2[(mt * 16 + r0) * 17 + w]     = make_float2(s0, q0);
                red2[(mt * 16 + 8 + r0) * 17 + w] = make_float2(s8, q8);
            }
        }
        __syncthreads();   // red ready

        // ---- per-row stats --------------------------------------------------
        {
            float s = 0.f, q = 0.f;
#pragma unroll
            for (int k = 0; k < 16; k++) {
                float2 p = red2[tid * 17 + k];
                s += p.x;
                q += p.y;
            }
            float mu = s * (1.0f / 256.0f);
            float var = fmaxf(q * (1.0f / 256.0f) - mu * mu, 0.0f);
            stat2[tid] = make_float2(mu, rsqrtf(var + 1e-5f));
        }
        __syncthreads();   // stats ready

        // ---- pass 2: normalize (L2-hot) -------------------------------------
        {
            const float4* lng4 = (const float4*)(spar + P_LNG);
            const float4* lnb4 = (const float4*)(spar + P_LNB);
            float4* out4 = (float4*)(out + rowbase * 256);
#pragma unroll 4
            for (int i = tid; i < ROWS_PER_CTA * 64; i += THREADS) {
                const int r = i >> 6, c4 = i & 63;
                float4 z = out4[i];
                float2 st = stat2[r];
                float4 gg = lng4[c4];
                float4 bb = lnb4[c4];
                z.x = fmaf((z.x - st.x) * st.y, gg.x, bb.x);
                z.y = fmaf((z.y - st.x) * st.y, gg.y, bb.y);
                z.z = fmaf((z.z - st.x) * st.y, gg.z, bb.z);
                z.w = fmaf((z.w - st.x) * st.y, gg.w, bb.w);
                out4[i] = z;
            }
        }
        __syncthreads();   // protect A overwrite vs stragglers in GEMM? (A reused next iter)
    }
}

// ---------------------------------------------------------------------------
extern "C" void kernel_launch(void* const* d_in, const int* in_sizes, int n_in,
                              void* d_out, int out_size) {
    const int* read_count  = (const int*)d_in[0];
    const int* write_count = (const int*)d_in[1];
    const int* fault_count = (const int*)d_in[2];
    const int* cow_count   = (const int*)d_in[3];
    const int* recency     = (const int*)d_in[4];
    const float* volatility  = (const float*)d_in[5];
    const float* pressure    = (const float*)d_in[6];
    const float* count_emb   = (const float*)d_in[7];
    const float* recency_emb = (const float*)d_in[8];
    const float* p_w1 = (const float*)d_in[9];
    const float* p_b1 = (const float*)d_in[10];
    const float* p_w2 = (const float*)d_in[11];
    const float* p_b2 = (const float*)d_in[12];
    const float* v_w1 = (const float*)d_in[13];
    const float* v_b1 = (const float*)d_in[14];
    const float* v_w2 = (const float*)d_in[15];
    const float* v_b2 = (const float*)d_in[16];
    const float* f_wh = (const float*)d_in[17];
    const float* f_bh = (const float*)d_in[18];
    const float* f_wg = (const float*)d_in[19];
    const float* f_bg = (const float*)d_in[20];
    const float* ln_g = (const float*)d_in[21];
    const float* ln_b = (const float*)d_in[22];
    float* out = (float*)d_out;

    const int B = in_sizes[0];
    const int num_tiles = B / ROWS_PER_CTA;  // 1024

    int dev = 0, sms = 148;
    cudaGetDevice(&dev);
    cudaDeviceGetAttribute(&sms, cudaDevAttrMultiProcessorCount, dev);
    int grid = num_tiles < sms ? num_tiles : sms;

    quant_prep_kernel<<<4, 512>>>(v_w1, v_w2, p_w1, p_w2);

    cudaFuncSetAttribute(encoder_hmma_kernel,
                         cudaFuncAttributeMaxDynamicSharedMemorySize, SMEM_BYTES);
    encoder_hmma_kernel<<<grid, THREADS, SMEM_BYTES>>>(
        read_count, write_count, fault_count, cow_count, recency,
        volatility, pressure, count_emb, recency_emb,
        p_b1, p_b2, v_b1, v_b2,
        f_wh, f_bh, f_wg, f_bg, ln_g, ln_b, out, num_tiles);
}